// round 1
// baseline (speedup 1.0000x reference)
#include <cuda_runtime.h>
#include <math.h>

#define D 32
#define F 64
#define MAXB 262144
#define MAXNE 500000

// Scratch (device globals — no allocation allowed)
__device__ float g_h_user[MAXB * D];
__device__ float g_h_item[MAXB * D];
__device__ float g_agg_user[MAXB * D];
__device__ float g_agg_item[MAXB * D];
__device__ float g_proj_ui[MAXNE * D];
__device__ float g_proj_iu[MAXNE * D];

// ---------------------------------------------------------------------------
// Kernel 1: h_user/h_item = mem[ids] @ W  (warp per node, shfl broadcast).
// Also zeroes agg accumulators (must happen every graph replay).
// ---------------------------------------------------------------------------
__global__ void k_h(const float* __restrict__ mem_user,
                    const float* __restrict__ mem_item,
                    const int* __restrict__ nid_user,
                    const int* __restrict__ nid_item,
                    const float* __restrict__ Wu,
                    const float* __restrict__ Wi,
                    int B) {
    __shared__ float sWu[D * D];
    __shared__ float sWi[D * D];
    int tid = threadIdx.x;
    for (int i = tid; i < D * D; i += blockDim.x) {
        sWu[i] = Wu[i];
        sWi[i] = Wi[i];
    }
    __syncthreads();
    int lane = tid & 31;
    int warp = tid >> 5;
    int r = blockIdx.x * 8 + warp;
    if (r >= B) return;
    int nu = nid_user[r];
    int ni = nid_item[r];
    float mu = mem_user[(size_t)nu * D + lane];
    float mi = mem_item[(size_t)ni * D + lane];
    float au = 0.f, ai = 0.f;
#pragma unroll
    for (int k = 0; k < D; k++) {
        float muk = __shfl_sync(0xffffffffu, mu, k);
        float mik = __shfl_sync(0xffffffffu, mi, k);
        au += muk * sWu[k * D + lane];
        ai += mik * sWi[k * D + lane];
    }
    size_t o = (size_t)r * D + lane;
    g_h_user[o] = au;
    g_h_item[o] = ai;
    g_agg_user[o] = 0.f;
    g_agg_item[o] = 0.f;
}

// ---------------------------------------------------------------------------
// Kernel 2: proj = edge_feature @ We + be, both edge types (blockIdx.y).
// Tile: 64 rows x 32 cols, block (16,8), thread computes 4x4.
// ---------------------------------------------------------------------------
__global__ void k_proj(const float* __restrict__ feat,
                       const float* __restrict__ We0, const float* __restrict__ be0,
                       const float* __restrict__ We1, const float* __restrict__ be1,
                       int NE) {
    const float* We = blockIdx.y ? We1 : We0;
    const float* be = blockIdx.y ? be1 : be0;
    float* out = blockIdx.y ? g_proj_iu : g_proj_ui;

    __shared__ float sA[64][65];     // 64 rows x 64 k (padded)
    __shared__ float sW[F * D];      // 64 x 32
    __shared__ float sb[D];

    int tx = threadIdx.x;            // 0..15 -> row groups
    int ty = threadIdx.y;            // 0..7  -> col groups
    int tid = ty * 16 + tx;
    int row0 = blockIdx.x * 64;

    for (int i = tid; i < (F * D) / 4; i += 128)
        ((float4*)sW)[i] = ((const float4*)We)[i];
    if (tid < D) sb[tid] = be[tid];

    for (int i = tid; i < 64 * 16; i += 128) {
        int r = i >> 4;
        int c4 = (i & 15) * 4;
        float4 v = make_float4(0.f, 0.f, 0.f, 0.f);
        int gr = row0 + r;
        if (gr < NE) v = *(const float4*)(feat + (size_t)gr * F + c4);
        sA[r][c4] = v.x; sA[r][c4 + 1] = v.y; sA[r][c4 + 2] = v.z; sA[r][c4 + 3] = v.w;
    }
    __syncthreads();

    float acc[4][4];
#pragma unroll
    for (int i = 0; i < 4; i++)
#pragma unroll
        for (int j = 0; j < 4; j++) acc[i][j] = sb[ty * 4 + j];

#pragma unroll 8
    for (int k = 0; k < F; k++) {
        float a[4], w[4];
#pragma unroll
        for (int i = 0; i < 4; i++) a[i] = sA[tx * 4 + i][k];
#pragma unroll
        for (int j = 0; j < 4; j++) w[j] = sW[k * D + ty * 4 + j];
#pragma unroll
        for (int i = 0; i < 4; i++)
#pragma unroll
            for (int j = 0; j < 4; j++) acc[i][j] += a[i] * w[j];
    }

#pragma unroll
    for (int i = 0; i < 4; i++) {
        int gr = row0 + tx * 4 + i;
        if (gr < NE) {
            float4 v = make_float4(acc[i][0], acc[i][1], acc[i][2], acc[i][3]);
            *(float4*)(out + (size_t)gr * D + ty * 4) = v;
        }
    }
}

// ---------------------------------------------------------------------------
// Kernel 3: per-edge message + scatter. 8 lanes per edge, lane handles 4
// consecutive output dims -> one red.global.add.v4.f32 per lane.
// ---------------------------------------------------------------------------
__global__ void k_edge(const int* __restrict__ src_ui, const int* __restrict__ dst_ui,
                       const int* __restrict__ idx_ui, const float* __restrict__ t_ui,
                       const int* __restrict__ src_iu, const int* __restrict__ dst_iu,
                       const int* __restrict__ idx_iu, const float* __restrict__ t_iu,
                       const float* __restrict__ time_w, const float* __restrict__ time_b,
                       int E) {
    int tid = threadIdx.x;
    int lane = tid & 31;
    int warp = tid >> 5;
    int q = lane & 7;        // dim group within edge
    int s = lane >> 3;       // edge slot within warp (0..3)
    long e = (long)blockIdx.x * 32 + warp * 4 + s;
    if (e >= 2L * E) return;

    const int *srcA, *dstA, *idxA;
    const float* tA;
    const float *h, *proj;
    float* agg;
    int ei;
    if (e < E) {
        ei = (int)e;
        srcA = src_ui; dstA = dst_ui; idxA = idx_ui; tA = t_ui;
        h = g_h_user; proj = g_proj_ui; agg = g_agg_item;
    } else {
        ei = (int)(e - E);
        srcA = src_iu; dstA = dst_iu; idxA = idx_iu; tA = t_iu;
        h = g_h_item; proj = g_proj_iu; agg = g_agg_user;
    }
    int srch = srcA[ei];
    int dst = dstA[ei];
    int fid = idxA[ei];
    float t = tA[ei];

    float4 hv = *(const float4*)(h + (size_t)srch * D + q * 4);
    float4 pv = *(const float4*)(proj + (size_t)fid * D + q * 4);
    float4 tw = *(const float4*)(time_w + q * 4);
    float4 tb = *(const float4*)(time_b + q * 4);

    float m0 = hv.x + pv.x + cosf(t * tw.x + tb.x);
    float m1 = hv.y + pv.y + cosf(t * tw.y + tb.y);
    float m2 = hv.z + pv.z + cosf(t * tw.z + tb.z);
    float m3 = hv.w + pv.w + cosf(t * tw.w + tb.w);

    float* p = agg + (size_t)dst * D + q * 4;
    asm volatile("red.global.add.v4.f32 [%0], {%1, %2, %3, %4};"
                 :: "l"(p), "f"(m0), "f"(m1), "f"(m2), "f"(m3) : "memory");
}

// ---------------------------------------------------------------------------
// Kernel 4: hu/hi = relu(h+agg); z=[hu,hi]; decoder 64->64->16->1.
// Block handles 64 nodes; block (16,16); layer1 as 4x4-microtile GEMM.
// ---------------------------------------------------------------------------
__global__ void k_final(const float* __restrict__ W1, const float* __restrict__ b1,
                        const float* __restrict__ W2, const float* __restrict__ b2,
                        const float* __restrict__ W3, const float* __restrict__ b3,
                        float* __restrict__ out, int B) {
    __shared__ float sZ[64][65];     // z, later reused for x1
    __shared__ float sW1[64 * 64];
    __shared__ float sW2[64 * 16];
    __shared__ float sW3[16];
    __shared__ float sb1[64];
    __shared__ float sb2[16];

    int tx = threadIdx.x;
    int ty = threadIdx.y;
    int tid = ty * 16 + tx;          // 0..255
    int n0 = blockIdx.x * 64;

    for (int i = tid; i < (64 * 64) / 4; i += 256)
        ((float4*)sW1)[i] = ((const float4*)W1)[i];
    for (int i = tid; i < (64 * 16) / 4; i += 256)
        ((float4*)sW2)[i] = ((const float4*)W2)[i];
    if (tid < 16) { sW3[tid] = W3[tid]; sb2[tid] = b2[tid]; }
    if (tid < 64) sb1[tid] = b1[tid];

    // stage z = [relu(hu+aggu), relu(hi+aggi)]
    for (int i = tid; i < 64 * 32; i += 256) {
        int n = i >> 5;
        int k = i & 31;
        float zu = 0.f, zi = 0.f;
        if (n0 + n < B) {
            size_t gi = (size_t)(n0 + n) * D + k;
            zu = g_h_user[gi] + g_agg_user[gi];
            zi = g_h_item[gi] + g_agg_item[gi];
        }
        sZ[n][k] = fmaxf(zu, 0.f);
        sZ[n][32 + k] = fmaxf(zi, 0.f);
    }
    __syncthreads();

    // layer 1: x1 = relu(z @ W1 + b1), thread computes 4 rows x 4 cols
    float acc[4][4];
#pragma unroll
    for (int i = 0; i < 4; i++)
#pragma unroll
        for (int j = 0; j < 4; j++) acc[i][j] = sb1[ty * 4 + j];

#pragma unroll 8
    for (int k = 0; k < 64; k++) {
        float a[4], w[4];
#pragma unroll
        for (int i = 0; i < 4; i++) a[i] = sZ[tx * 4 + i][k];
#pragma unroll
        for (int j = 0; j < 4; j++) w[j] = sW1[k * 64 + ty * 4 + j];
#pragma unroll
        for (int i = 0; i < 4; i++)
#pragma unroll
            for (int j = 0; j < 4; j++) acc[i][j] += a[i] * w[j];
    }
    __syncthreads();

    // x1 (relu) back into sZ
#pragma unroll
    for (int i = 0; i < 4; i++)
#pragma unroll
        for (int j = 0; j < 4; j++)
            sZ[tx * 4 + i][ty * 4 + j] = fmaxf(acc[i][j], 0.f);
    __syncthreads();

    // layers 2+3: thread t -> node tid/4, col group (tid%4)*4
    int n = tid >> 2;
    int c0 = (tid & 3) * 4;
    float a2[4];
#pragma unroll
    for (int j = 0; j < 4; j++) a2[j] = sb2[c0 + j];
#pragma unroll 8
    for (int k = 0; k < 64; k++) {
        float x = sZ[n][k];
#pragma unroll
        for (int j = 0; j < 4; j++) a2[j] += x * sW2[k * 16 + c0 + j];
    }
    float part = 0.f;
#pragma unroll
    for (int j = 0; j < 4; j++) part += fmaxf(a2[j], 0.f) * sW3[c0 + j];
    part += __shfl_xor_sync(0xffffffffu, part, 1);
    part += __shfl_xor_sync(0xffffffffu, part, 2);
    if ((tid & 3) == 0 && (n0 + n) < B) out[n0 + n] = part + b3[0];
}

// ---------------------------------------------------------------------------
// Launch. Detect input ordering (reference-arg order vs setup_inputs order).
// ---------------------------------------------------------------------------
extern "C" void kernel_launch(void* const* d_in, const int* in_sizes, int n_in,
                              void* d_out, int out_size) {
    // reference-arg order: d_in[2] = edge_feature (32M elems)
    // setup_inputs order:  d_in[2] = node_ids_user (262144 elems)
    bool refOrder = in_sizes[2] > 1000000;

    int iMemU, iMemI, iFeat, iTui, iTiu, iWu, iWi, iWeUI, iBeUI, iWeIU, iBeIU;
    int iTw, iTb, iW1, iB1, iW2, iB2, iW3, iB3;
    int iNidU, iNidI, iSrcUI, iDstUI, iSrcIU, iDstIU, iIdxUI, iIdxIU;

    if (refOrder) {
        iMemU = 0;  iMemI = 1;  iFeat = 2;  iTui = 3;  iTiu = 4;
        iWu = 5;    iWi = 6;    iWeUI = 7;  iBeUI = 8; iWeIU = 9; iBeIU = 10;
        iTw = 11;   iTb = 12;
        iW1 = 13;   iB1 = 14;   iW2 = 15;   iB2 = 16;  iW3 = 17;  iB3 = 18;
        iNidU = 19; iNidI = 20;
        iSrcUI = 21; iDstUI = 22; iSrcIU = 23; iDstIU = 24; iIdxUI = 25; iIdxIU = 26;
    } else {
        iMemU = 0;  iMemI = 1;  iNidU = 2;  iNidI = 3;
        iSrcUI = 4; iDstUI = 5; iSrcIU = 6; iDstIU = 7; iIdxUI = 8; iIdxIU = 9;
        iTui = 10;  iTiu = 11;  iFeat = 12;
        iWu = 13;   iWi = 14;   iWeUI = 15; iBeUI = 16; iWeIU = 17; iBeIU = 18;
        iTw = 19;   iTb = 20;
        iW1 = 21;   iB1 = 22;   iW2 = 23;   iB2 = 24;   iW3 = 25;  iB3 = 26;
    }

    const float* mem_user = (const float*)d_in[iMemU];
    const float* mem_item = (const float*)d_in[iMemI];
    const float* feat     = (const float*)d_in[iFeat];
    const float* t_ui     = (const float*)d_in[iTui];
    const float* t_iu     = (const float*)d_in[iTiu];
    const float* Wu       = (const float*)d_in[iWu];
    const float* Wi       = (const float*)d_in[iWi];
    const float* WeUI     = (const float*)d_in[iWeUI];
    const float* beUI     = (const float*)d_in[iBeUI];
    const float* WeIU     = (const float*)d_in[iWeIU];
    const float* beIU     = (const float*)d_in[iBeIU];
    const float* tw       = (const float*)d_in[iTw];
    const float* tb       = (const float*)d_in[iTb];
    const float* W1       = (const float*)d_in[iW1];
    const float* b1       = (const float*)d_in[iB1];
    const float* W2       = (const float*)d_in[iW2];
    const float* b2       = (const float*)d_in[iB2];
    const float* W3       = (const float*)d_in[iW3];
    const float* b3       = (const float*)d_in[iB3];
    const int* nid_user   = (const int*)d_in[iNidU];
    const int* nid_item   = (const int*)d_in[iNidI];
    const int* src_ui     = (const int*)d_in[iSrcUI];
    const int* dst_ui     = (const int*)d_in[iDstUI];
    const int* src_iu     = (const int*)d_in[iSrcIU];
    const int* dst_iu     = (const int*)d_in[iDstIU];
    const int* idx_ui     = (const int*)d_in[iIdxUI];
    const int* idx_iu     = (const int*)d_in[iIdxIU];

    int B  = in_sizes[iNidU];
    int E  = in_sizes[iSrcUI];
    int NE = in_sizes[iFeat] / F;

    k_h<<<(B + 7) / 8, 256>>>(mem_user, mem_item, nid_user, nid_item, Wu, Wi, B);

    dim3 gp((NE + 63) / 64, 2);
    k_proj<<<gp, dim3(16, 8)>>>(feat, WeUI, beUI, WeIU, beIU, NE);

    long total_edges = 2L * E;
    int nb_e = (int)((total_edges + 31) / 32);
    k_edge<<<nb_e, 256>>>(src_ui, dst_ui, idx_ui, t_ui,
                          src_iu, dst_iu, idx_iu, t_iu,
                          tw, tb, E);

    k_final<<<(B + 63) / 64, dim3(16, 16)>>>(W1, b1, W2, b2, W3, b3,
                                             (float*)d_out, B);
}

// round 2
// speedup vs baseline: 1.1261x; 1.1261x over previous
#include <cuda_runtime.h>
#include <math.h>

#define D 32
#define F 64
#define MAXB 262144
#define MAXNE 500000

// Scratch (device globals — no allocation allowed)
__device__ float g_h_user[MAXB * D];
__device__ float g_h_item[MAXB * D];
__device__ float g_agg_user[MAXB * D];   // initialized to h_user, edges add in
__device__ float g_agg_item[MAXB * D];   // initialized to h_item
__device__ float g_proj_ui[MAXNE * D];
__device__ float g_proj_iu[MAXNE * D];

// ---------------------------------------------------------------------------
// Kernel 1: h = mem[ids] @ W (warp per node, shfl broadcast).
// agg is initialized to h so k_final only needs relu(agg).
// ---------------------------------------------------------------------------
__global__ void k_h(const float* __restrict__ mem_user,
                    const float* __restrict__ mem_item,
                    const int* __restrict__ nid_user,
                    const int* __restrict__ nid_item,
                    const float* __restrict__ Wu,
                    const float* __restrict__ Wi,
                    int B) {
    __shared__ float sWu[D * D];
    __shared__ float sWi[D * D];
    int tid = threadIdx.x;
    for (int i = tid; i < D * D; i += blockDim.x) {
        sWu[i] = Wu[i];
        sWi[i] = Wi[i];
    }
    __syncthreads();
    int lane = tid & 31;
    int warp = tid >> 5;
    int r = blockIdx.x * 8 + warp;
    if (r >= B) return;
    int nu = nid_user[r];
    int ni = nid_item[r];
    float mu = mem_user[(size_t)nu * D + lane];
    float mi = mem_item[(size_t)ni * D + lane];
    float au = 0.f, ai = 0.f;
#pragma unroll
    for (int k = 0; k < D; k++) {
        float muk = __shfl_sync(0xffffffffu, mu, k);
        float mik = __shfl_sync(0xffffffffu, mi, k);
        au += muk * sWu[k * D + lane];
        ai += mik * sWi[k * D + lane];
    }
    size_t o = (size_t)r * D + lane;
    g_h_user[o] = au;
    g_h_item[o] = ai;
    g_agg_user[o] = au;
    g_agg_item[o] = ai;
}

// ---------------------------------------------------------------------------
// Kernel 2: proj = feat @ We + be for BOTH edge types in one pass.
// Tile: 128 rows x 64 cols (ui cols 0..31, iu cols 32..63).
// Block (16,8) = 128 threads, each computes an 8x8 microtile with
// float4 LDS on both operands (feat staged transposed).
// ---------------------------------------------------------------------------
__global__ void k_proj(const float* __restrict__ feat,
                       const float* __restrict__ We0, const float* __restrict__ be0,
                       const float* __restrict__ We1, const float* __restrict__ be1,
                       int NE) {
    __shared__ float sAT[64][132];   // [k][row], padded
    __shared__ float sW[64 * 64];    // [k][col] : col<32 -> ui, col>=32 -> iu
    __shared__ float sb[64];

    int tx = threadIdx.x;            // 0..15 -> 8 rows each
    int ty = threadIdx.y;            // 0..7  -> 8 cols each
    int tid = ty * 16 + tx;
    int row0 = blockIdx.x * 128;

    // weights: sW[k][c]
    for (int i = tid; i < 64 * 16; i += 128) {
        int k = i >> 4;
        int c4 = (i & 15) * 4;
        float4 v = (c4 < 32) ? *(const float4*)(We0 + k * 32 + c4)
                             : *(const float4*)(We1 + k * 32 + (c4 - 32));
        *(float4*)(sW + k * 64 + c4) = v;
    }
    if (tid < 32) { sb[tid] = be0[tid]; sb[32 + tid] = be1[tid]; }

    // stage feat transposed: sAT[k][r]
    for (int i = tid; i < 128 * 16; i += 128) {
        int r = i >> 4;
        int kc = i & 15;
        int gr = row0 + r;
        float4 v = make_float4(0.f, 0.f, 0.f, 0.f);
        if (gr < NE) v = *(const float4*)(feat + (size_t)gr * F + kc * 4);
        int k0 = kc * 4;
        sAT[k0 + 0][r] = v.x;
        sAT[k0 + 1][r] = v.y;
        sAT[k0 + 2][r] = v.z;
        sAT[k0 + 3][r] = v.w;
    }
    __syncthreads();

    float acc[8][8];
#pragma unroll
    for (int i = 0; i < 8; i++)
#pragma unroll
        for (int j = 0; j < 8; j++) acc[i][j] = sb[ty * 8 + j];

#pragma unroll 4
    for (int k = 0; k < F; k++) {
        float4 a0 = *(const float4*)(&sAT[k][tx * 8]);
        float4 a1 = *(const float4*)(&sAT[k][tx * 8 + 4]);
        float4 w0 = *(const float4*)(&sW[k * 64 + ty * 8]);
        float4 w1 = *(const float4*)(&sW[k * 64 + ty * 8 + 4]);
        float a[8] = {a0.x, a0.y, a0.z, a0.w, a1.x, a1.y, a1.z, a1.w};
        float w[8] = {w0.x, w0.y, w0.z, w0.w, w1.x, w1.y, w1.z, w1.w};
#pragma unroll
        for (int i = 0; i < 8; i++)
#pragma unroll
            for (int j = 0; j < 8; j++) acc[i][j] += a[i] * w[j];
    }

#pragma unroll
    for (int i = 0; i < 8; i++) {
        int gr = row0 + tx * 8 + i;
        if (gr < NE) {
            float4 v0 = make_float4(acc[i][0], acc[i][1], acc[i][2], acc[i][3]);
            float4 v1 = make_float4(acc[i][4], acc[i][5], acc[i][6], acc[i][7]);
            if (ty < 4) {
                *(float4*)(g_proj_ui + (size_t)gr * D + ty * 8) = v0;
                *(float4*)(g_proj_ui + (size_t)gr * D + ty * 8 + 4) = v1;
            } else {
                *(float4*)(g_proj_iu + (size_t)gr * D + (ty - 4) * 8) = v0;
                *(float4*)(g_proj_iu + (size_t)gr * D + (ty - 4) * 8 + 4) = v1;
            }
        }
    }
}

// ---------------------------------------------------------------------------
// Kernel 3: per-edge message + scatter. 8 lanes per edge, lane handles 4
// consecutive output dims -> one red.global.add.v4.f32 per lane.
// ---------------------------------------------------------------------------
__global__ void k_edge(const int* __restrict__ src_ui, const int* __restrict__ dst_ui,
                       const int* __restrict__ idx_ui, const float* __restrict__ t_ui,
                       const int* __restrict__ src_iu, const int* __restrict__ dst_iu,
                       const int* __restrict__ idx_iu, const float* __restrict__ t_iu,
                       const float* __restrict__ time_w, const float* __restrict__ time_b,
                       int E) {
    int tid = threadIdx.x;
    int lane = tid & 31;
    int warp = tid >> 5;
    int q = lane & 7;        // dim group within edge
    int s = lane >> 3;       // edge slot within warp (0..3)
    long e = (long)blockIdx.x * 32 + warp * 4 + s;
    if (e >= 2L * E) return;

    const int *srcA, *dstA, *idxA;
    const float* tA;
    const float *h, *proj;
    float* agg;
    int ei;
    if (e < E) {
        ei = (int)e;
        srcA = src_ui; dstA = dst_ui; idxA = idx_ui; tA = t_ui;
        h = g_h_user; proj = g_proj_ui; agg = g_agg_item;
    } else {
        ei = (int)(e - E);
        srcA = src_iu; dstA = dst_iu; idxA = idx_iu; tA = t_iu;
        h = g_h_item; proj = g_proj_iu; agg = g_agg_user;
    }
    int srch = srcA[ei];
    int dst = dstA[ei];
    int fid = idxA[ei];
    float t = tA[ei];

    float4 hv = *(const float4*)(h + (size_t)srch * D + q * 4);
    float4 pv = *(const float4*)(proj + (size_t)fid * D + q * 4);
    float4 tw = *(const float4*)(time_w + q * 4);
    float4 tb = *(const float4*)(time_b + q * 4);

    float m0 = hv.x + pv.x + cosf(t * tw.x + tb.x);
    float m1 = hv.y + pv.y + cosf(t * tw.y + tb.y);
    float m2 = hv.z + pv.z + cosf(t * tw.z + tb.z);
    float m3 = hv.w + pv.w + cosf(t * tw.w + tb.w);

    float* p = agg + (size_t)dst * D + q * 4;
    asm volatile("red.global.add.v4.f32 [%0], {%1, %2, %3, %4};"
                 :: "l"(p), "f"(m0), "f"(m1), "f"(m2), "f"(m3) : "memory");
}

// ---------------------------------------------------------------------------
// Kernel 4: z = [relu(agg_user), relu(agg_item)] (agg pre-seeded with h);
// decoder 64->64->16->1. Block (16,8)=128 threads handles 128 nodes.
// Layer1 as 8x8-microtile GEMM with float4 LDS (z staged transposed).
// ---------------------------------------------------------------------------
__global__ void k_final(const float* __restrict__ W1, const float* __restrict__ b1,
                        const float* __restrict__ W2, const float* __restrict__ b2,
                        const float* __restrict__ W3, const float* __restrict__ b3,
                        float* __restrict__ out, int B) {
    __shared__ float sZ[64][132];    // [k][node]; reused for x1 transposed
    __shared__ float sW1[64 * 64];
    __shared__ float sW2[64 * 16];
    __shared__ float sW3[16];
    __shared__ float sb1[64];
    __shared__ float sb2[16];
    __shared__ float sb3;

    int tx = threadIdx.x;            // 0..15 -> 8 nodes each
    int ty = threadIdx.y;            // 0..7  -> 8 cols each
    int tid = ty * 16 + tx;          // 0..127
    int n0 = blockIdx.x * 128;

    for (int i = tid; i < (64 * 64) / 4; i += 128)
        ((float4*)sW1)[i] = ((const float4*)W1)[i];
    for (int i = tid; i < (64 * 16) / 4; i += 128)
        ((float4*)sW2)[i] = ((const float4*)W2)[i];
    if (tid < 16) { sW3[tid] = W3[tid]; sb2[tid] = b2[tid]; }
    if (tid < 64) sb1[tid] = b1[tid];
    if (tid == 0) sb3 = b3[0];

    // stage z transposed with relu: k 0..31 from agg_user, 32..63 from agg_item
    for (int i = tid; i < 128 * 16; i += 128) {
        int n = i >> 4;
        int kc = i & 15;
        int node = n0 + n;
        float4 v = make_float4(0.f, 0.f, 0.f, 0.f);
        if (node < B) {
            v = (kc < 8) ? *(const float4*)(g_agg_user + (size_t)node * D + kc * 4)
                         : *(const float4*)(g_agg_item + (size_t)node * D + (kc - 8) * 4);
        }
        int k0 = kc * 4;
        sZ[k0 + 0][n] = fmaxf(v.x, 0.f);
        sZ[k0 + 1][n] = fmaxf(v.y, 0.f);
        sZ[k0 + 2][n] = fmaxf(v.z, 0.f);
        sZ[k0 + 3][n] = fmaxf(v.w, 0.f);
    }
    __syncthreads();

    // layer 1: x1 = relu(z @ W1 + b1), 8x8 microtile
    float acc[8][8];
#pragma unroll
    for (int i = 0; i < 8; i++)
#pragma unroll
        for (int j = 0; j < 8; j++) acc[i][j] = sb1[ty * 8 + j];

#pragma unroll 4
    for (int k = 0; k < 64; k++) {
        float4 a0 = *(const float4*)(&sZ[k][tx * 8]);
        float4 a1 = *(const float4*)(&sZ[k][tx * 8 + 4]);
        float4 w0 = *(const float4*)(&sW1[k * 64 + ty * 8]);
        float4 w1 = *(const float4*)(&sW1[k * 64 + ty * 8 + 4]);
        float a[8] = {a0.x, a0.y, a0.z, a0.w, a1.x, a1.y, a1.z, a1.w};
        float w[8] = {w0.x, w0.y, w0.z, w0.w, w1.x, w1.y, w1.z, w1.w};
#pragma unroll
        for (int i = 0; i < 8; i++)
#pragma unroll
            for (int j = 0; j < 8; j++) acc[i][j] += a[i] * w[j];
    }
    __syncthreads();   // everyone done reading sZ

    // x1 (relu) back into sZ transposed: sZ[col][node]
#pragma unroll
    for (int i = 0; i < 8; i++)
#pragma unroll
        for (int j = 0; j < 8; j++)
            sZ[ty * 8 + j][tx * 8 + i] = fmaxf(acc[i][j], 0.f);
    __syncthreads();

    // layers 2+3: one node per thread
    {
        int node = n0 + tid;
        float a2[16];
#pragma unroll
        for (int j = 0; j < 16; j++) a2[j] = sb2[j];
#pragma unroll 8
        for (int k = 0; k < 64; k++) {
            float x = sZ[k][tid];
            float4 w0 = *(const float4*)(&sW2[k * 16]);
            float4 w1 = *(const float4*)(&sW2[k * 16 + 4]);
            float4 w2 = *(const float4*)(&sW2[k * 16 + 8]);
            float4 w3 = *(const float4*)(&sW2[k * 16 + 12]);
            a2[0] += x * w0.x;  a2[1] += x * w0.y;  a2[2] += x * w0.z;  a2[3] += x * w0.w;
            a2[4] += x * w1.x;  a2[5] += x * w1.y;  a2[6] += x * w1.z;  a2[7] += x * w1.w;
            a2[8] += x * w2.x;  a2[9] += x * w2.y;  a2[10] += x * w2.z; a2[11] += x * w2.w;
            a2[12] += x * w3.x; a2[13] += x * w3.y; a2[14] += x * w3.z; a2[15] += x * w3.w;
        }
        float r = sb3;
#pragma unroll
        for (int j = 0; j < 16; j++) r += fmaxf(a2[j], 0.f) * sW3[j];
        if (node < B) out[node] = r;
    }
}

// ---------------------------------------------------------------------------
// Launch. Detect input ordering (reference-arg order vs setup_inputs order).
// ---------------------------------------------------------------------------
extern "C" void kernel_launch(void* const* d_in, const int* in_sizes, int n_in,
                              void* d_out, int out_size) {
    bool refOrder = in_sizes[2] > 1000000;

    int iMemU, iMemI, iFeat, iTui, iTiu, iWu, iWi, iWeUI, iBeUI, iWeIU, iBeIU;
    int iTw, iTb, iW1, iB1, iW2, iB2, iW3, iB3;
    int iNidU, iNidI, iSrcUI, iDstUI, iSrcIU, iDstIU, iIdxUI, iIdxIU;

    if (refOrder) {
        iMemU = 0;  iMemI = 1;  iFeat = 2;  iTui = 3;  iTiu = 4;
        iWu = 5;    iWi = 6;    iWeUI = 7;  iBeUI = 8; iWeIU = 9; iBeIU = 10;
        iTw = 11;   iTb = 12;
        iW1 = 13;   iB1 = 14;   iW2 = 15;   iB2 = 16;  iW3 = 17;  iB3 = 18;
        iNidU = 19; iNidI = 20;
        iSrcUI = 21; iDstUI = 22; iSrcIU = 23; iDstIU = 24; iIdxUI = 25; iIdxIU = 26;
    } else {
        iMemU = 0;  iMemI = 1;  iNidU = 2;  iNidI = 3;
        iSrcUI = 4; iDstUI = 5; iSrcIU = 6; iDstIU = 7; iIdxUI = 8; iIdxIU = 9;
        iTui = 10;  iTiu = 11;  iFeat = 12;
        iWu = 13;   iWi = 14;   iWeUI = 15; iBeUI = 16; iWeIU = 17; iBeIU = 18;
        iTw = 19;   iTb = 20;
        iW1 = 21;   iB1 = 22;   iW2 = 23;   iB2 = 24;   iW3 = 25;  iB3 = 26;
    }

    const float* mem_user = (const float*)d_in[iMemU];
    const float* mem_item = (const float*)d_in[iMemI];
    const float* feat     = (const float*)d_in[iFeat];
    const float* t_ui     = (const float*)d_in[iTui];
    const float* t_iu     = (const float*)d_in[iTiu];
    const float* Wu       = (const float*)d_in[iWu];
    const float* Wi       = (const float*)d_in[iWi];
    const float* WeUI     = (const float*)d_in[iWeUI];
    const float* beUI     = (const float*)d_in[iBeUI];
    const float* WeIU     = (const float*)d_in[iWeIU];
    const float* beIU     = (const float*)d_in[iBeIU];
    const float* tw       = (const float*)d_in[iTw];
    const float* tb       = (const float*)d_in[iTb];
    const float* W1       = (const float*)d_in[iW1];
    const float* b1       = (const float*)d_in[iB1];
    const float* W2       = (const float*)d_in[iW2];
    const float* b2       = (const float*)d_in[iB2];
    const float* W3       = (const float*)d_in[iW3];
    const float* b3       = (const float*)d_in[iB3];
    const int* nid_user   = (const int*)d_in[iNidU];
    const int* nid_item   = (const int*)d_in[iNidI];
    const int* src_ui     = (const int*)d_in[iSrcUI];
    const int* dst_ui     = (const int*)d_in[iDstUI];
    const int* src_iu     = (const int*)d_in[iSrcIU];
    const int* dst_iu     = (const int*)d_in[iDstIU];
    const int* idx_ui     = (const int*)d_in[iIdxUI];
    const int* idx_iu     = (const int*)d_in[iIdxIU];

    int B  = in_sizes[iNidU];
    int E  = in_sizes[iSrcUI];
    int NE = in_sizes[iFeat] / F;

    k_h<<<(B + 7) / 8, 256>>>(mem_user, mem_item, nid_user, nid_item, Wu, Wi, B);

    k_proj<<<(NE + 127) / 128, dim3(16, 8)>>>(feat, WeUI, beUI, WeIU, beIU, NE);

    long total_edges = 2L * E;
    int nb_e = (int)((total_edges + 31) / 32);
    k_edge<<<nb_e, 256>>>(src_ui, dst_ui, idx_ui, t_ui,
                          src_iu, dst_iu, idx_iu, t_iu,
                          tw, tb, E);

    k_final<<<(B + 127) / 128, dim3(16, 8)>>>(W1, b1, W2, b2, W3, b3,
                                              (float*)d_out, B);
}

// round 5
// speedup vs baseline: 1.2064x; 1.0713x over previous
#include <cuda_runtime.h>
#include <cuda_fp16.h>
#include <math.h>

#define D 32
#define F 64
#define MAXB 262144
#define MAXNE 500000

// Scratch (device globals — no allocation allowed)
__device__ float g_h_user[MAXB * D];
__device__ float g_h_item[MAXB * D];
__device__ float g_agg_user[MAXB * D];   // seeded with h_user, edges add in
__device__ float g_agg_item[MAXB * D];   // seeded with h_item
__device__ __half g_proj_ui[MAXNE * D];  // fp16 storage halves gather traffic
__device__ __half g_proj_iu[MAXNE * D];

// ---------------------------------------------------------------------------
// Kernel 1: h = mem[ids] @ W (warp per node, shfl broadcast).
// agg is seeded with h so k_final only needs relu(agg).
// ---------------------------------------------------------------------------
__global__ void k_h(const float* __restrict__ mem_user,
                    const float* __restrict__ mem_item,
                    const int* __restrict__ nid_user,
                    const int* __restrict__ nid_item,
                    const float* __restrict__ Wu,
                    const float* __restrict__ Wi,
                    int B) {
    __shared__ float sWu[D * D];
    __shared__ float sWi[D * D];
    int tid = threadIdx.x;
    for (int i = tid; i < D * D; i += blockDim.x) {
        sWu[i] = Wu[i];
        sWi[i] = Wi[i];
    }
    __syncthreads();
    int lane = tid & 31;
    int warp = tid >> 5;
    int r = blockIdx.x * 8 + warp;
    if (r >= B) return;
    int nu = nid_user[r];
    int ni = nid_item[r];
    float mu = mem_user[(size_t)nu * D + lane];
    float mi = mem_item[(size_t)ni * D + lane];
    float au = 0.f, ai = 0.f;
#pragma unroll
    for (int k = 0; k < D; k++) {
        float muk = __shfl_sync(0xffffffffu, mu, k);
        float mik = __shfl_sync(0xffffffffu, mi, k);
        au += muk * sWu[k * D + lane];
        ai += mik * sWi[k * D + lane];
    }
    size_t o = (size_t)r * D + lane;
    g_h_user[o] = au;
    g_h_item[o] = ai;
    g_agg_user[o] = au;
    g_agg_item[o] = ai;
}

// ---------------------------------------------------------------------------
// Kernel 2: proj = feat @ We + be for BOTH edge types in one pass.
// Tile: 128 rows x 64 cols (ui cols 0..31, iu cols 32..63).
// Block (16,8) = 128 threads, 8x8 microtile, fp32 compute, fp16 output.
// ---------------------------------------------------------------------------
__global__ void k_proj(const float* __restrict__ feat,
                       const float* __restrict__ We0, const float* __restrict__ be0,
                       const float* __restrict__ We1, const float* __restrict__ be1,
                       int NE) {
    __shared__ float sAT[64][132];   // [k][row], padded
    __shared__ float sW[64 * 64];    // [k][col] : col<32 -> ui, col>=32 -> iu
    __shared__ float sb[64];

    int tx = threadIdx.x;            // 0..15 -> 8 rows each
    int ty = threadIdx.y;            // 0..7  -> 8 cols each
    int tid = ty * 16 + tx;
    int row0 = blockIdx.x * 128;

    for (int i = tid; i < 64 * 16; i += 128) {
        int k = i >> 4;
        int c4 = (i & 15) * 4;
        float4 v = (c4 < 32) ? *(const float4*)(We0 + k * 32 + c4)
                             : *(const float4*)(We1 + k * 32 + (c4 - 32));
        *(float4*)(sW + k * 64 + c4) = v;
    }
    if (tid < 32) { sb[tid] = be0[tid]; sb[32 + tid] = be1[tid]; }

    for (int i = tid; i < 128 * 16; i += 128) {
        int r = i >> 4;
        int kc = i & 15;
        int gr = row0 + r;
        float4 v = make_float4(0.f, 0.f, 0.f, 0.f);
        if (gr < NE) v = *(const float4*)(feat + (size_t)gr * F + kc * 4);
        int k0 = kc * 4;
        sAT[k0 + 0][r] = v.x;
        sAT[k0 + 1][r] = v.y;
        sAT[k0 + 2][r] = v.z;
        sAT[k0 + 3][r] = v.w;
    }
    __syncthreads();

    float acc[8][8];
#pragma unroll
    for (int i = 0; i < 8; i++)
#pragma unroll
        for (int j = 0; j < 8; j++) acc[i][j] = sb[ty * 8 + j];

#pragma unroll 4
    for (int k = 0; k < F; k++) {
        float4 a0 = *(const float4*)(&sAT[k][tx * 8]);
        float4 a1 = *(const float4*)(&sAT[k][tx * 8 + 4]);
        float4 w0 = *(const float4*)(&sW[k * 64 + ty * 8]);
        float4 w1 = *(const float4*)(&sW[k * 64 + ty * 8 + 4]);
        float a[8] = {a0.x, a0.y, a0.z, a0.w, a1.x, a1.y, a1.z, a1.w};
        float w[8] = {w0.x, w0.y, w0.z, w0.w, w1.x, w1.y, w1.z, w1.w};
#pragma unroll
        for (int i = 0; i < 8; i++)
#pragma unroll
            for (int j = 0; j < 8; j++) acc[i][j] += a[i] * w[j];
    }

#pragma unroll
    for (int i = 0; i < 8; i++) {
        int gr = row0 + tx * 8 + i;
        if (gr < NE) {
            __half2 h0 = __floats2half2_rn(acc[i][0], acc[i][1]);
            __half2 h1 = __floats2half2_rn(acc[i][2], acc[i][3]);
            __half2 h2 = __floats2half2_rn(acc[i][4], acc[i][5]);
            __half2 h3 = __floats2half2_rn(acc[i][6], acc[i][7]);
            uint4 v;
            v.x = *(unsigned*)&h0; v.y = *(unsigned*)&h1;
            v.z = *(unsigned*)&h2; v.w = *(unsigned*)&h3;
            if (ty < 4)
                *(uint4*)(g_proj_ui + (size_t)gr * D + ty * 8) = v;
            else
                *(uint4*)(g_proj_iu + (size_t)gr * D + (ty - 4) * 8) = v;
        }
    }
}

// ---------------------------------------------------------------------------
// Kernel 3: per-edge message + scatter. 8 lanes per edge, lane handles 4
// consecutive output dims -> one red.global.add.v4.f32 per lane.
// ---------------------------------------------------------------------------
__global__ void k_edge(const int* __restrict__ src_ui, const int* __restrict__ dst_ui,
                       const int* __restrict__ idx_ui, const float* __restrict__ t_ui,
                       const int* __restrict__ src_iu, const int* __restrict__ dst_iu,
                       const int* __restrict__ idx_iu, const float* __restrict__ t_iu,
                       const float* __restrict__ time_w, const float* __restrict__ time_b,
                       int E) {
    int tid = threadIdx.x;
    int lane = tid & 31;
    int warp = tid >> 5;
    int q = lane & 7;        // dim group within edge
    int s = lane >> 3;       // edge slot within warp (0..3)
    long e = (long)blockIdx.x * 32 + warp * 4 + s;
    if (e >= 2L * E) return;

    const int *srcA, *dstA, *idxA;
    const float* tA;
    const float* h;
    const __half* proj;
    float* agg;
    int ei;
    if (e < E) {
        ei = (int)e;
        srcA = src_ui; dstA = dst_ui; idxA = idx_ui; tA = t_ui;
        h = g_h_user; proj = g_proj_ui; agg = g_agg_item;
    } else {
        ei = (int)(e - E);
        srcA = src_iu; dstA = dst_iu; idxA = idx_iu; tA = t_iu;
        h = g_h_item; proj = g_proj_iu; agg = g_agg_user;
    }
    int srch = srcA[ei];
    int dst = dstA[ei];
    int fid = idxA[ei];
    float t = tA[ei];

    float4 hv = *(const float4*)(h + (size_t)srch * D + q * 4);
    const __half2* pp = (const __half2*)(proj + (size_t)fid * D + q * 4);
    float2 p01 = __half22float2(pp[0]);
    float2 p23 = __half22float2(pp[1]);
    float4 tw = *(const float4*)(time_w + q * 4);
    float4 tb = *(const float4*)(time_b + q * 4);

    float m0 = hv.x + p01.x + __cosf(fmaf(t, tw.x, tb.x));
    float m1 = hv.y + p01.y + __cosf(fmaf(t, tw.y, tb.y));
    float m2 = hv.z + p23.x + __cosf(fmaf(t, tw.z, tb.z));
    float m3 = hv.w + p23.y + __cosf(fmaf(t, tw.w, tb.w));

    float* p = agg + (size_t)dst * D + q * 4;
    asm volatile("red.global.add.v4.f32 [%0], {%1, %2, %3, %4};"
                 :: "l"(p), "f"(m0), "f"(m1), "f"(m2), "f"(m3) : "memory");
}

// ---------------------------------------------------------------------------
// Kernel 4: z = [relu(agg_user), relu(agg_item)]; decoder 64->64->16->1.
// Block (16,16)=256 threads, 128-node tile, 8x4 microtile for layer 1.
// ---------------------------------------------------------------------------
__global__ void k_final(const float* __restrict__ W1, const float* __restrict__ b1,
                        const float* __restrict__ W2, const float* __restrict__ b2,
                        const float* __restrict__ W3, const float* __restrict__ b3,
                        float* __restrict__ out, int B) {
    __shared__ float sZ[64][132];    // [k][node]; reused for x1 transposed
    __shared__ float sW1[64 * 64];
    __shared__ float sW2[64 * 16];
    __shared__ float sW3[16];
    __shared__ float sb1[64];
    __shared__ float sb2[16];
    __shared__ float sb3;

    int tx = threadIdx.x;            // 0..15 -> 8 nodes each
    int ty = threadIdx.y;            // 0..15 -> 4 cols each
    int tid = ty * 16 + tx;          // 0..255
    int n0 = blockIdx.x * 128;

    for (int i = tid; i < (64 * 64) / 4; i += 256)
        ((float4*)sW1)[i] = ((const float4*)W1)[i];
    for (int i = tid; i < (64 * 16) / 4; i += 256)
        ((float4*)sW2)[i] = ((const float4*)W2)[i];
    if (tid < 16) { sW3[tid] = W3[tid]; sb2[tid] = b2[tid]; }
    if (tid < 64) sb1[tid] = b1[tid];
    if (tid == 0) sb3 = b3[0];

    // stage z transposed with relu
    for (int i = tid; i < 128 * 16; i += 256) {
        int n = i >> 4;
        int kc = i & 15;
        int node = n0 + n;
        float4 v = make_float4(0.f, 0.f, 0.f, 0.f);
        if (node < B) {
            v = (kc < 8) ? *(const float4*)(g_agg_user + (size_t)node * D + kc * 4)
                         : *(const float4*)(g_agg_item + (size_t)node * D + (kc - 8) * 4);
        }
        int k0 = kc * 4;
        sZ[k0 + 0][n] = fmaxf(v.x, 0.f);
        sZ[k0 + 1][n] = fmaxf(v.y, 0.f);
        sZ[k0 + 2][n] = fmaxf(v.z, 0.f);
        sZ[k0 + 3][n] = fmaxf(v.w, 0.f);
    }
    __syncthreads();

    // layer 1: x1 = relu(z @ W1 + b1), 8 nodes x 4 cols per thread
    float acc[8][4];
#pragma unroll
    for (int i = 0; i < 8; i++)
#pragma unroll
        for (int j = 0; j < 4; j++) acc[i][j] = sb1[ty * 4 + j];

#pragma unroll 4
    for (int k = 0; k < 64; k++) {
        float4 a0 = *(const float4*)(&sZ[k][tx * 8]);
        float4 a1 = *(const float4*)(&sZ[k][tx * 8 + 4]);
        float4 w0 = *(const float4*)(&sW1[k * 64 + ty * 4]);
        float a[8] = {a0.x, a0.y, a0.z, a0.w, a1.x, a1.y, a1.z, a1.w};
        float w[4] = {w0.x, w0.y, w0.z, w0.w};
#pragma unroll
        for (int i = 0; i < 8; i++)
#pragma unroll
            for (int j = 0; j < 4; j++) acc[i][j] += a[i] * w[j];
    }
    __syncthreads();   // everyone done reading sZ

    // x1 (relu) back into sZ transposed: sZ[col][node]
#pragma unroll
    for (int i = 0; i < 8; i++)
#pragma unroll
        for (int j = 0; j < 4; j++)
            sZ[ty * 4 + j][tx * 8 + i] = fmaxf(acc[i][j], 0.f);
    __syncthreads();

    // layers 2+3: 2 threads per node (each 8 of the 16 mid cols)
    {
        int n = tid >> 1;
        int half = tid & 1;
        int node = n0 + n;
        float a2[8];
#pragma unroll
        for (int j = 0; j < 8; j++) a2[j] = sb2[half * 8 + j];
#pragma unroll 8
        for (int k = 0; k < 64; k++) {
            float x = sZ[k][n];
            float4 w0 = *(const float4*)(&sW2[k * 16 + half * 8]);
            float4 w1 = *(const float4*)(&sW2[k * 16 + half * 8 + 4]);
            a2[0] += x * w0.x; a2[1] += x * w0.y; a2[2] += x * w0.z; a2[3] += x * w0.w;
            a2[4] += x * w1.x; a2[5] += x * w1.y; a2[6] += x * w1.z; a2[7] += x * w1.w;
        }
        float part = 0.f;
#pragma unroll
        for (int j = 0; j < 8; j++) part += fmaxf(a2[j], 0.f) * sW3[half * 8 + j];
        part += __shfl_xor_sync(0xffffffffu, part, 1);
        if (half == 0 && node < B) out[node] = part + sb3;
    }
}

// ---------------------------------------------------------------------------
// Launch. Detect input ordering (reference-arg order vs setup_inputs order).
// ---------------------------------------------------------------------------
extern "C" void kernel_launch(void* const* d_in, const int* in_sizes, int n_in,
                              void* d_out, int out_size) {
    bool refOrder = in_sizes[2] > 1000000;

    int iMemU, iMemI, iFeat, iTui, iTiu, iWu, iWi, iWeUI, iBeUI, iWeIU, iBeIU;
    int iTw, iTb, iW1, iB1, iW2, iB2, iW3, iB3;
    int iNidU, iNidI, iSrcUI, iDstUI, iSrcIU, iDstIU, iIdxUI, iIdxIU;

    if (refOrder) {
        iMemU = 0;  iMemI = 1;  iFeat = 2;  iTui = 3;  iTiu = 4;
        iWu = 5;    iWi = 6;    iWeUI = 7;  iBeUI = 8; iWeIU = 9; iBeIU = 10;
        iTw = 11;   iTb = 12;
        iW1 = 13;   iB1 = 14;   iW2 = 15;   iB2 = 16;  iW3 = 17;  iB3 = 18;
        iNidU = 19; iNidI = 20;
        iSrcUI = 21; iDstUI = 22; iSrcIU = 23; iDstIU = 24; iIdxUI = 25; iIdxIU = 26;
    } else {
        iMemU = 0;  iMemI = 1;  iNidU = 2;  iNidI = 3;
        iSrcUI = 4; iDstUI = 5; iSrcIU = 6; iDstIU = 7; iIdxUI = 8; iIdxIU = 9;
        iTui = 10;  iTiu = 11;  iFeat = 12;
        iWu = 13;   iWi = 14;   iWeUI = 15; iBeUI = 16; iWeIU = 17; iBeIU = 18;
        iTw = 19;   iTb = 20;
        iW1 = 21;   iB1 = 22;   iW2 = 23;   iB2 = 24;   iW3 = 25;  iB3 = 26;
    }

    const float* mem_user = (const float*)d_in[iMemU];
    const float* mem_item = (const float*)d_in[iMemI];
    const float* feat     = (const float*)d_in[iFeat];
    const float* t_ui     = (const float*)d_in[iTui];
    const float* t_iu     = (const float*)d_in[iTiu];
    const float* Wu       = (const float*)d_in[iWu];
    const float* Wi       = (const float*)d_in[iWi];
    const float* WeUI     = (const float*)d_in[iWeUI];
    const float* beUI     = (const float*)d_in[iBeUI];
    const float* WeIU     = (const float*)d_in[iWeIU];
    const float* beIU     = (const float*)d_in[iBeIU];
    const float* tw       = (const float*)d_in[iTw];
    const float* tb       = (const float*)d_in[iTb];
    const float* W1       = (const float*)d_in[iW1];
    const float* b1       = (const float*)d_in[iB1];
    const float* W2       = (const float*)d_in[iW2];
    const float* b2       = (const float*)d_in[iB2];
    const float* W3       = (const float*)d_in[iW3];
    const float* b3       = (const float*)d_in[iB3];
    const int* nid_user   = (const int*)d_in[iNidU];
    const int* nid_item   = (const int*)d_in[iNidI];
    const int* src_ui     = (const int*)d_in[iSrcUI];
    const int* dst_ui     = (const int*)d_in[iDstUI];
    const int* src_iu     = (const int*)d_in[iSrcIU];
    const int* dst_iu     = (const int*)d_in[iDstIU];
    const int* idx_ui     = (const int*)d_in[iIdxUI];
    const int* idx_iu     = (const int*)d_in[iIdxIU];

    int B  = in_sizes[iNidU];
    int E  = in_sizes[iSrcUI];
    int NE = in_sizes[iFeat] / F;

    k_h<<<(B + 7) / 8, 256>>>(mem_user, mem_item, nid_user, nid_item, Wu, Wi, B);

    k_proj<<<(NE + 127) / 128, dim3(16, 8)>>>(feat, WeUI, beUI, WeIU, beIU, NE);

    long total_edges = 2L * E;
    int nb_e = (int)((total_edges + 31) / 32);
    k_edge<<<nb_e, 256>>>(src_ui, dst_ui, idx_ui, t_ui,
                          src_iu, dst_iu, idx_iu, t_iu,
                          tw, tb, E);

    k_final<<<(B + 127) / 128, dim3(16, 16)>>>(W1, b1, W2, b2, W3, b3,
                                               (float*)d_out, B);
}

// round 6
// speedup vs baseline: 1.6188x; 1.3418x over previous
#include <cuda_runtime.h>
#include <cuda_fp16.h>
#include <math.h>

#define D 32
#define F 64
#define MAXB 262144
#define MAXNE 500000

// Scratch (device globals — no allocation allowed)
__device__ float g_h_user[MAXB * D];
__device__ float g_h_item[MAXB * D];
__device__ float g_agg_user[MAXB * D];   // seeded with h_user, edges add in
__device__ float g_agg_item[MAXB * D];   // seeded with h_item
__device__ __half g_proj_ui[MAXNE * D];  // fp16 storage halves gather traffic
__device__ __half g_proj_iu[MAXNE * D];

// ---------------------------------------------------------------------------
// mma.m16n8k16 fp16 -> fp32 helper
// ---------------------------------------------------------------------------
__device__ __forceinline__ void mma_16816(float* c, unsigned a0, unsigned a1,
                                          unsigned a2, unsigned a3,
                                          unsigned b0, unsigned b1) {
    asm volatile(
        "mma.sync.aligned.m16n8k16.row.col.f32.f16.f16.f32 "
        "{%0,%1,%2,%3}, {%4,%5,%6,%7}, {%8,%9}, {%0,%1,%2,%3};"
        : "+f"(c[0]), "+f"(c[1]), "+f"(c[2]), "+f"(c[3])
        : "r"(a0), "r"(a1), "r"(a2), "r"(a3), "r"(b0), "r"(b1));
}

// ---------------------------------------------------------------------------
// Kernel 1: h = mem[ids] @ W (warp per node, shfl broadcast).
// agg is seeded with h so k_final only needs relu(agg).
// ---------------------------------------------------------------------------
__global__ void k_h(const float* __restrict__ mem_user,
                    const float* __restrict__ mem_item,
                    const int* __restrict__ nid_user,
                    const int* __restrict__ nid_item,
                    const float* __restrict__ Wu,
                    const float* __restrict__ Wi,
                    int B) {
    __shared__ float sWu[D * D];
    __shared__ float sWi[D * D];
    int tid = threadIdx.x;
    for (int i = tid; i < D * D; i += blockDim.x) {
        sWu[i] = Wu[i];
        sWi[i] = Wi[i];
    }
    __syncthreads();
    int lane = tid & 31;
    int warp = tid >> 5;
    int r = blockIdx.x * 8 + warp;
    if (r >= B) return;
    int nu = nid_user[r];
    int ni = nid_item[r];
    float mu = mem_user[(size_t)nu * D + lane];
    float mi = mem_item[(size_t)ni * D + lane];
    float au = 0.f, ai = 0.f;
#pragma unroll
    for (int k = 0; k < D; k++) {
        float muk = __shfl_sync(0xffffffffu, mu, k);
        float mik = __shfl_sync(0xffffffffu, mi, k);
        au += muk * sWu[k * D + lane];
        ai += mik * sWi[k * D + lane];
    }
    size_t o = (size_t)r * D + lane;
    g_h_user[o] = au;
    g_h_item[o] = ai;
    g_agg_user[o] = au;
    g_agg_item[o] = ai;
}

// ---------------------------------------------------------------------------
// Kernel 2: proj = feat @ We + be for BOTH edge types, tensor cores.
// Tile: 128 rows x 64 cols (cols 0..31 -> ui, 32..63 -> iu), K=64.
// Block 256 threads = 8 warps; warp w does rows [w*16, w*16+16).
// A staged fp16 [128][72], W^T staged fp16 [64][72] (k contiguous).
// ---------------------------------------------------------------------------
__global__ void k_proj(const float* __restrict__ feat,
                       const float* __restrict__ We0, const float* __restrict__ be0,
                       const float* __restrict__ We1, const float* __restrict__ be1,
                       int NE) {
    __shared__ __half sA[128 * 72];      // [row][k], pad 72
    __shared__ __half sWT[64 * 72];      // [n][k],  pad 72
    __shared__ float sb[64];

    int tid = threadIdx.x;
    int row0 = blockIdx.x * 128;

    // stage W^T as fp16: sWT[n][k] = We(k, n)
    for (int i = tid; i < 64 * 64; i += 256) {
        int k = i >> 6;
        int n = i & 63;
        float v = (n < 32) ? We0[k * 32 + n] : We1[k * 32 + (n - 32)];
        sWT[n * 72 + k] = __float2half_rn(v);
    }
    if (tid < 32) { sb[tid] = be0[tid]; sb[32 + tid] = be1[tid]; }

    // stage feat rows as fp16
    for (int i = tid; i < 128 * 16; i += 256) {
        int r = i >> 4;
        int k0 = (i & 15) * 4;
        int gr = row0 + r;
        float4 v = make_float4(0.f, 0.f, 0.f, 0.f);
        if (gr < NE) v = *(const float4*)(feat + (size_t)gr * F + k0);
        __half2 h01 = __floats2half2_rn(v.x, v.y);
        __half2 h23 = __floats2half2_rn(v.z, v.w);
        uint2 pk;
        pk.x = *(unsigned*)&h01;
        pk.y = *(unsigned*)&h23;
        *(uint2*)(sA + r * 72 + k0) = pk;
    }
    __syncthreads();

    int lane = tid & 31;
    int warp = tid >> 5;
    int g = lane >> 2;       // 0..7
    int tig = lane & 3;      // 0..3

    const unsigned* Aw = (const unsigned*)sA;    // 36 words per row
    const unsigned* Ww = (const unsigned*)sWT;   // 36 words per n

    float acc[8][4];
#pragma unroll
    for (int t = 0; t < 8; t++) {
        float bc0 = sb[t * 8 + 2 * tig];
        float bc1 = sb[t * 8 + 2 * tig + 1];
        acc[t][0] = bc0; acc[t][1] = bc1; acc[t][2] = bc0; acc[t][3] = bc1;
    }

    int r0 = warp * 16 + g;
#pragma unroll
    for (int ks = 0; ks < 4; ks++) {
        unsigned a0 = Aw[r0 * 36 + ks * 8 + tig];
        unsigned a1 = Aw[(r0 + 8) * 36 + ks * 8 + tig];
        unsigned a2 = Aw[r0 * 36 + ks * 8 + tig + 4];
        unsigned a3 = Aw[(r0 + 8) * 36 + ks * 8 + tig + 4];
#pragma unroll
        for (int t = 0; t < 8; t++) {
            unsigned b0 = Ww[(t * 8 + g) * 36 + ks * 8 + tig];
            unsigned b1 = Ww[(t * 8 + g) * 36 + ks * 8 + tig + 4];
            mma_16816(acc[t], a0, a1, a2, a3, b0, b1);
        }
    }

    // store: c0,c1 -> (row, col..col+1); c2,c3 -> (row+8, col..col+1)
    int rowA = row0 + warp * 16 + g;
    int rowB = rowA + 8;
#pragma unroll
    for (int t = 0; t < 8; t++) {
        int col = t * 8 + 2 * tig;
        __half2 hA = __floats2half2_rn(acc[t][0], acc[t][1]);
        __half2 hB = __floats2half2_rn(acc[t][2], acc[t][3]);
        if (col < 32) {
            if (rowA < NE) *(__half2*)(g_proj_ui + (size_t)rowA * D + col) = hA;
            if (rowB < NE) *(__half2*)(g_proj_ui + (size_t)rowB * D + col) = hB;
        } else {
            int c = col - 32;
            if (rowA < NE) *(__half2*)(g_proj_iu + (size_t)rowA * D + c) = hA;
            if (rowB < NE) *(__half2*)(g_proj_iu + (size_t)rowB * D + c) = hB;
        }
    }
}

// ---------------------------------------------------------------------------
// Kernel 3: per-edge message + scatter. 8 lanes per edge, lane handles 4
// consecutive output dims -> one red.global.add.v4.f32 per lane.
// ---------------------------------------------------------------------------
__global__ void k_edge(const int* __restrict__ src_ui, const int* __restrict__ dst_ui,
                       const int* __restrict__ idx_ui, const float* __restrict__ t_ui,
                       const int* __restrict__ src_iu, const int* __restrict__ dst_iu,
                       const int* __restrict__ idx_iu, const float* __restrict__ t_iu,
                       const float* __restrict__ time_w, const float* __restrict__ time_b,
                       int E) {
    int tid = threadIdx.x;
    int lane = tid & 31;
    int warp = tid >> 5;
    int q = lane & 7;        // dim group within edge
    int s = lane >> 3;       // edge slot within warp (0..3)
    long e = (long)blockIdx.x * 32 + warp * 4 + s;
    if (e >= 2L * E) return;

    const int *srcA, *dstA, *idxA;
    const float* tA;
    const float* h;
    const __half* proj;
    float* agg;
    int ei;
    if (e < E) {
        ei = (int)e;
        srcA = src_ui; dstA = dst_ui; idxA = idx_ui; tA = t_ui;
        h = g_h_user; proj = g_proj_ui; agg = g_agg_item;
    } else {
        ei = (int)(e - E);
        srcA = src_iu; dstA = dst_iu; idxA = idx_iu; tA = t_iu;
        h = g_h_item; proj = g_proj_iu; agg = g_agg_user;
    }
    int srch = srcA[ei];
    int dst = dstA[ei];
    int fid = idxA[ei];
    float t = tA[ei];

    float4 hv = *(const float4*)(h + (size_t)srch * D + q * 4);
    const __half2* pp = (const __half2*)(proj + (size_t)fid * D + q * 4);
    float2 p01 = __half22float2(pp[0]);
    float2 p23 = __half22float2(pp[1]);
    float4 tw = *(const float4*)(time_w + q * 4);
    float4 tb = *(const float4*)(time_b + q * 4);

    float m0 = hv.x + p01.x + __cosf(fmaf(t, tw.x, tb.x));
    float m1 = hv.y + p01.y + __cosf(fmaf(t, tw.y, tb.y));
    float m2 = hv.z + p23.x + __cosf(fmaf(t, tw.z, tb.z));
    float m3 = hv.w + p23.y + __cosf(fmaf(t, tw.w, tb.w));

    float* p = agg + (size_t)dst * D + q * 4;
    asm volatile("red.global.add.v4.f32 [%0], {%1, %2, %3, %4};"
                 :: "l"(p), "f"(m0), "f"(m1), "f"(m2), "f"(m3) : "memory");
}

// ---------------------------------------------------------------------------
// Kernel 4: z = [relu(agg_user), relu(agg_item)] staged fp16; layer-1 GEMM
// (128x64 @ 64x64) on tensor cores; layers 2+3 scalar fp32.
// Block 256 threads = 8 warps, 128-node tile.
// ---------------------------------------------------------------------------
__global__ void k_final(const float* __restrict__ W1, const float* __restrict__ b1,
                        const float* __restrict__ W2, const float* __restrict__ b2,
                        const float* __restrict__ W3, const float* __restrict__ b3,
                        float* __restrict__ out, int B) {
    __shared__ __half sA[128 * 72];   // z fp16: [node][k], pad 72
    __shared__ __half sW1T[64 * 72];  // [n][k], pad 72
    __shared__ __half sX[64 * 136];   // x1 fp16: [col][node], pad 136
    __shared__ float sW2[64 * 16];
    __shared__ float sW3[16];
    __shared__ float sb1[64];
    __shared__ float sb2[16];
    __shared__ float sb3;

    int tid = threadIdx.x;
    int n0 = blockIdx.x * 128;

    // stage W1^T fp16
    for (int i = tid; i < 64 * 64; i += 256) {
        int k = i >> 6;
        int n = i & 63;
        sW1T[n * 72 + k] = __float2half_rn(W1[k * 64 + n]);
    }
    for (int i = tid; i < (64 * 16) / 4; i += 256)
        ((float4*)sW2)[i] = ((const float4*)W2)[i];
    if (tid < 16) { sW3[tid] = W3[tid]; sb2[tid] = b2[tid]; }
    if (tid < 64) sb1[tid] = b1[tid];
    if (tid == 0) sb3 = b3[0];

    // stage z = relu(agg) as fp16: [node][0..31 user | 32..63 item]
    for (int i = tid; i < 128 * 16; i += 256) {
        int n = i >> 4;
        int kc = i & 15;
        int node = n0 + n;
        float4 v = make_float4(0.f, 0.f, 0.f, 0.f);
        if (node < B) {
            v = (kc < 8) ? *(const float4*)(g_agg_user + (size_t)node * D + kc * 4)
                         : *(const float4*)(g_agg_item + (size_t)node * D + (kc - 8) * 4);
        }
        __half2 h01 = __floats2half2_rn(fmaxf(v.x, 0.f), fmaxf(v.y, 0.f));
        __half2 h23 = __floats2half2_rn(fmaxf(v.z, 0.f), fmaxf(v.w, 0.f));
        uint2 pk;
        pk.x = *(unsigned*)&h01;
        pk.y = *(unsigned*)&h23;
        *(uint2*)(sA + n * 72 + kc * 4) = pk;
    }
    __syncthreads();

    int lane = tid & 31;
    int warp = tid >> 5;
    int g = lane >> 2;
    int tig = lane & 3;

    const unsigned* Aw = (const unsigned*)sA;
    const unsigned* Ww = (const unsigned*)sW1T;

    float acc[8][4];
#pragma unroll
    for (int t = 0; t < 8; t++) {
        float bc0 = sb1[t * 8 + 2 * tig];
        float bc1 = sb1[t * 8 + 2 * tig + 1];
        acc[t][0] = bc0; acc[t][1] = bc1; acc[t][2] = bc0; acc[t][3] = bc1;
    }

    int r0 = warp * 16 + g;
#pragma unroll
    for (int ks = 0; ks < 4; ks++) {
        unsigned a0 = Aw[r0 * 36 + ks * 8 + tig];
        unsigned a1 = Aw[(r0 + 8) * 36 + ks * 8 + tig];
        unsigned a2 = Aw[r0 * 36 + ks * 8 + tig + 4];
        unsigned a3 = Aw[(r0 + 8) * 36 + ks * 8 + tig + 4];
#pragma unroll
        for (int t = 0; t < 8; t++) {
            unsigned b0 = Ww[(t * 8 + g) * 36 + ks * 8 + tig];
            unsigned b1 = Ww[(t * 8 + g) * 36 + ks * 8 + tig + 4];
            mma_16816(acc[t], a0, a1, a2, a3, b0, b1);
        }
    }

    // x1 = relu(acc) -> sX[col][node] fp16
    int nA = warp * 16 + g;
    int nB = nA + 8;
#pragma unroll
    for (int t = 0; t < 8; t++) {
        int col = t * 8 + 2 * tig;
        sX[col * 136 + nA] = __float2half(fmaxf(acc[t][0], 0.f));
        sX[(col + 1) * 136 + nA] = __float2half(fmaxf(acc[t][1], 0.f));
        sX[col * 136 + nB] = __float2half(fmaxf(acc[t][2], 0.f));
        sX[(col + 1) * 136 + nB] = __float2half(fmaxf(acc[t][3], 0.f));
    }
    __syncthreads();

    // layers 2+3: 2 threads per node (each 8 of the 16 mid cols)
    {
        int n = tid >> 1;
        int half = tid & 1;
        int node = n0 + n;
        float a2[8];
#pragma unroll
        for (int j = 0; j < 8; j++) a2[j] = sb2[half * 8 + j];
#pragma unroll 8
        for (int k = 0; k < 64; k++) {
            float x = __half2float(sX[k * 136 + n]);
            float4 w0 = *(const float4*)(&sW2[k * 16 + half * 8]);
            float4 w1 = *(const float4*)(&sW2[k * 16 + half * 8 + 4]);
            a2[0] += x * w0.x; a2[1] += x * w0.y; a2[2] += x * w0.z; a2[3] += x * w0.w;
            a2[4] += x * w1.x; a2[5] += x * w1.y; a2[6] += x * w1.z; a2[7] += x * w1.w;
        }
        float part = 0.f;
#pragma unroll
        for (int j = 0; j < 8; j++) part += fmaxf(a2[j], 0.f) * sW3[half * 8 + j];
        part += __shfl_xor_sync(0xffffffffu, part, 1);
        if (half == 0 && node < B) out[node] = part + sb3;
    }
}

// ---------------------------------------------------------------------------
// Launch. Detect input ordering (reference-arg order vs setup_inputs order).
// ---------------------------------------------------------------------------
extern "C" void kernel_launch(void* const* d_in, const int* in_sizes, int n_in,
                              void* d_out, int out_size) {
    bool refOrder = in_sizes[2] > 1000000;

    int iMemU, iMemI, iFeat, iTui, iTiu, iWu, iWi, iWeUI, iBeUI, iWeIU, iBeIU;
    int iTw, iTb, iW1, iB1, iW2, iB2, iW3, iB3;
    int iNidU, iNidI, iSrcUI, iDstUI, iSrcIU, iDstIU, iIdxUI, iIdxIU;

    if (refOrder) {
        iMemU = 0;  iMemI = 1;  iFeat = 2;  iTui = 3;  iTiu = 4;
        iWu = 5;    iWi = 6;    iWeUI = 7;  iBeUI = 8; iWeIU = 9; iBeIU = 10;
        iTw = 11;   iTb = 12;
        iW1 = 13;   iB1 = 14;   iW2 = 15;   iB2 = 16;  iW3 = 17;  iB3 = 18;
        iNidU = 19; iNidI = 20;
        iSrcUI = 21; iDstUI = 22; iSrcIU = 23; iDstIU = 24; iIdxUI = 25; iIdxIU = 26;
    } else {
        iMemU = 0;  iMemI = 1;  iNidU = 2;  iNidI = 3;
        iSrcUI = 4; iDstUI = 5; iSrcIU = 6; iDstIU = 7; iIdxUI = 8; iIdxIU = 9;
        iTui = 10;  iTiu = 11;  iFeat = 12;
        iWu = 13;   iWi = 14;   iWeUI = 15; iBeUI = 16; iWeIU = 17; iBeIU = 18;
        iTw = 19;   iTb = 20;
        iW1 = 21;   iB1 = 22;   iW2 = 23;   iB2 = 24;   iW3 = 25;  iB3 = 26;
    }

    const float* mem_user = (const float*)d_in[iMemU];
    const float* mem_item = (const float*)d_in[iMemI];
    const float* feat     = (const float*)d_in[iFeat];
    const float* t_ui     = (const float*)d_in[iTui];
    const float* t_iu     = (const float*)d_in[iTiu];
    const float* Wu       = (const float*)d_in[iWu];
    const float* Wi       = (const float*)d_in[iWi];
    const float* WeUI     = (const float*)d_in[iWeUI];
    const float* beUI     = (const float*)d_in[iBeUI];
    const float* WeIU     = (const float*)d_in[iWeIU];
    const float* beIU     = (const float*)d_in[iBeIU];
    const float* tw       = (const float*)d_in[iTw];
    const float* tb       = (const float*)d_in[iTb];
    const float* W1       = (const float*)d_in[iW1];
    const float* b1       = (const float*)d_in[iB1];
    const float* W2       = (const float*)d_in[iW2];
    const float* b2       = (const float*)d_in[iB2];
    const float* W3       = (const float*)d_in[iW3];
    const float* b3       = (const float*)d_in[iB3];
    const int* nid_user   = (const int*)d_in[iNidU];
    const int* nid_item   = (const int*)d_in[iNidI];
    const int* src_ui     = (const int*)d_in[iSrcUI];
    const int* dst_ui     = (const int*)d_in[iDstUI];
    const int* src_iu     = (const int*)d_in[iSrcIU];
    const int* dst_iu     = (const int*)d_in[iDstIU];
    const int* idx_ui     = (const int*)d_in[iIdxUI];
    const int* idx_iu     = (const int*)d_in[iIdxIU];

    int B  = in_sizes[iNidU];
    int E  = in_sizes[iSrcUI];
    int NE = in_sizes[iFeat] / F;

    k_h<<<(B + 7) / 8, 256>>>(mem_user, mem_item, nid_user, nid_item, Wu, Wi, B);

    k_proj<<<(NE + 127) / 128, 256>>>(feat, WeUI, beUI, WeIU, beIU, NE);

    long total_edges = 2L * E;
    int nb_e = (int)((total_edges + 31) / 32);
    k_edge<<<nb_e, 256>>>(src_ui, dst_ui, idx_ui, t_ui,
                          src_iu, dst_iu, idx_iu, t_iu,
                          tw, tb, E);

    k_final<<<(B + 127) / 128, 256>>>(W1, b1, W2, b2, W3, b3,
                                      (float*)d_out, B);
}